// round 4
// baseline (speedup 1.0000x reference)
#include <cuda_runtime.h>
#include <math.h>

#define DIM   1024
#define NH    16
#define HD    64
#define SEQ   2048
#define BATCH 2
#define ROWS  (BATCH * SEQ)      // 4096
#define QSCALE 0.125f            // HD^-0.5

// ---------------- scratch (static device globals; no allocation) -------------
__device__ float g_q[ROWS * DIM];
__device__ float g_k[ROWS * DIM];
__device__ float g_v[ROWS * DIM];
__device__ float g_o[ROWS * DIM];
__device__ float g_h[ROWS * DIM];
__device__ float g_kv[BATCH * NH * HD * HD];   // per (b,h): 64x64

// ---------------- tiled fp32 SGEMM: C[M,N] = A[M,K] @ W[N,K]^T + epilogue ----
// BM=128 BN=128 BK=16, 256 threads, 8x8 per-thread micro tile.
#define BM 128
#define BN 128
#define BK 16
#define TM 8
#define TN 8

enum { EPI_PLAIN = 0, EPI_QSCALE = 1, EPI_GELU = 2, EPI_RESID = 3 };

template <int EPI>
__global__ __launch_bounds__(256) void sgemm_nt(
    const float* __restrict__ A, const float* __restrict__ W,
    const float* __restrict__ bias, float* __restrict__ C,
    int M, int N, int K,
    const float* __restrict__ r1, const float* __restrict__ r2)
{
    __shared__ float As[BK][BM];
    __shared__ float Ws[BK][BN];

    const int tid  = threadIdx.x;
    const int row0 = blockIdx.y * BM;
    const int col0 = blockIdx.x * BN;

    // global->shared load mapping (float4)
    const int lr = tid >> 2;          // 0..63
    const int lc = (tid & 3) * 4;     // 0,4,8,12

    // compute mapping
    const int tr = (tid >> 4) * TM;   // 0..120
    const int tc = (tid & 15) * TN;   // 0..120

    float acc[TM][TN] = {};
    float ra[TM], rw[TN];

    for (int k0 = 0; k0 < K; k0 += BK) {
        #pragma unroll
        for (int r = 0; r < BM; r += 64) {
            float4 t = *reinterpret_cast<const float4*>(
                &A[(size_t)(row0 + lr + r) * K + k0 + lc]);
            As[lc + 0][lr + r] = t.x; As[lc + 1][lr + r] = t.y;
            As[lc + 2][lr + r] = t.z; As[lc + 3][lr + r] = t.w;
        }
        #pragma unroll
        for (int r = 0; r < BN; r += 64) {
            float4 t = *reinterpret_cast<const float4*>(
                &W[(size_t)(col0 + lr + r) * K + k0 + lc]);
            Ws[lc + 0][lr + r] = t.x; Ws[lc + 1][lr + r] = t.y;
            Ws[lc + 2][lr + r] = t.z; Ws[lc + 3][lr + r] = t.w;
        }
        __syncthreads();
        #pragma unroll
        for (int kk = 0; kk < BK; kk++) {
            #pragma unroll
            for (int i = 0; i < TM; i++) ra[i] = As[kk][tr + i];
            #pragma unroll
            for (int j = 0; j < TN; j++) rw[j] = Ws[kk][tc + j];
            #pragma unroll
            for (int i = 0; i < TM; i++)
                #pragma unroll
                for (int j = 0; j < TN; j++)
                    acc[i][j] += ra[i] * rw[j];
        }
        __syncthreads();
    }

    float bj[TN];
    #pragma unroll
    for (int j = 0; j < TN; j++) bj[j] = bias[col0 + tc + j];

    #pragma unroll
    for (int i = 0; i < TM; i++) {
        const int row = row0 + tr + i;
        #pragma unroll
        for (int j = 0; j < TN; j++) {
            const int col = col0 + tc + j;
            float v = acc[i][j] + bj[j];
            if (EPI == EPI_QSCALE) {
                v *= QSCALE;
            } else if (EPI == EPI_GELU) {
                v = 0.5f * v * (1.0f + erff(v * 0.70710678118654752f));
            } else if (EPI == EPI_RESID) {
                size_t idx = (size_t)row * N + col;
                v += r1[idx] + r2[idx];
            }
            C[(size_t)row * N + col] = v;
        }
    }
}

// ---------------- zero KV ----------------------------------------------------
__global__ void zero_kv_kernel()
{
    int i = blockIdx.x * blockDim.x + threadIdx.x;
    g_kv[i] = 0.0f;
}

// ---------------- KV[b,h] = sum_s k[b,s,h,:]^T v[b,s,h,:] --------------------
// grid: (B*NH, 8 chunks of 256 seq rows), 256 threads.
__global__ __launch_bounds__(256) void kv_kernel()
{
    const int bh = blockIdx.x;
    const int b  = bh / NH;
    const int h  = bh % NH;
    const int s0 = blockIdx.y * 256;
    const int tid = threadIdx.x;

    __shared__ float ks[8][64];
    __shared__ float vs[8][64];

    const int d1 = (tid >> 4) * 4;   // 0..60
    const int d2 = (tid & 15) * 4;   // 0..60

    float acc[4][4] = {};

    const size_t base = (size_t)b * SEQ * DIM + h * HD;
    const int lrow = tid >> 5;            // 0..7
    const int lcol = (tid & 31) * 2;      // 0..62

    for (int s = s0; s < s0 + 256; s += 8) {
        const float* kr = g_k + base + (size_t)(s + lrow) * DIM;
        const float* vr = g_v + base + (size_t)(s + lrow) * DIM;
        *reinterpret_cast<float2*>(&ks[lrow][lcol]) =
            *reinterpret_cast<const float2*>(&kr[lcol]);
        *reinterpret_cast<float2*>(&vs[lrow][lcol]) =
            *reinterpret_cast<const float2*>(&vr[lcol]);
        __syncthreads();
        #pragma unroll
        for (int ss = 0; ss < 8; ss++) {
            float ka[4], va[4];
            float4 k4 = *reinterpret_cast<const float4*>(&ks[ss][d1]);
            float4 v4 = *reinterpret_cast<const float4*>(&vs[ss][d2]);
            ka[0] = k4.x; ka[1] = k4.y; ka[2] = k4.z; ka[3] = k4.w;
            va[0] = v4.x; va[1] = v4.y; va[2] = v4.z; va[3] = v4.w;
            #pragma unroll
            for (int i = 0; i < 4; i++)
                #pragma unroll
                for (int j = 0; j < 4; j++)
                    acc[i][j] += ka[i] * va[j];
        }
        __syncthreads();
    }

    float* dst = g_kv + (size_t)bh * (HD * HD);
    #pragma unroll
    for (int i = 0; i < 4; i++)
        #pragma unroll
        for (int j = 0; j < 4; j++)
            atomicAdd(&dst[(d1 + i) * HD + d2 + j], acc[i][j]);
}

// ---------------- out[b,s,h,:] = q[b,s,h,:] @ KV[b,h] ------------------------
// grid: (ROWS/64 row tiles, NH heads), 256 threads. 4x4 micro tile / thread.
__global__ __launch_bounds__(256) void attn_out_kernel()
{
    const int h  = blockIdx.y;
    const int r0 = blockIdx.x * 64;
    const int b  = r0 >> 11;            // r0 / SEQ
    const int tid = threadIdx.x;

    __shared__ float kvs[64][64];       // kvs[d][c]
    __shared__ float qs[64][65];        // qs[d][row] (transposed, padded)

    // load KV tile (4096 floats)
    {
        const float4* src = reinterpret_cast<const float4*>(
            g_kv + (size_t)(b * NH + h) * (HD * HD));
        float4* dst = reinterpret_cast<float4*>(&kvs[0][0]);
        for (int i = tid; i < 1024; i += 256) dst[i] = src[i];
    }
    // load q tile transposed: qs[d][r]
    for (int i = tid; i < 1024; i += 256) {
        int r  = i >> 4;         // 0..63
        int c4 = (i & 15) * 4;   // 0..60
        float4 t = *reinterpret_cast<const float4*>(
            &g_q[(size_t)(r0 + r) * DIM + h * HD + c4]);
        qs[c4 + 0][r] = t.x; qs[c4 + 1][r] = t.y;
        qs[c4 + 2][r] = t.z; qs[c4 + 3][r] = t.w;
    }
    __syncthreads();

    const int r4 = (tid >> 4) * 4;   // row offset 0..60
    const int c4 = (tid & 15) * 4;   // col offset 0..60

    float acc[4][4] = {};
    #pragma unroll 4
    for (int d = 0; d < 64; d++) {
        float qv[4];
        #pragma unroll
        for (int i = 0; i < 4; i++) qv[i] = qs[d][r4 + i];
        float4 kv4 = *reinterpret_cast<const float4*>(&kvs[d][c4]);
        float kvv[4] = {kv4.x, kv4.y, kv4.z, kv4.w};
        #pragma unroll
        for (int i = 0; i < 4; i++)
            #pragma unroll
            for (int j = 0; j < 4; j++)
                acc[i][j] += qv[i] * kvv[j];
    }

    #pragma unroll
    for (int i = 0; i < 4; i++) {
        float4 o = make_float4(acc[i][0], acc[i][1], acc[i][2], acc[i][3]);
        *reinterpret_cast<float4*>(
            &g_o[(size_t)(r0 + r4 + i) * DIM + h * HD + c4]) = o;
    }
}

// ---------------- launch -----------------------------------------------------
extern "C" void kernel_launch(void* const* d_in, const int* in_sizes, int n_in,
                              void* d_out, int out_size)
{
    const float* x  = (const float*)d_in[0];
    const float* Wq = (const float*)d_in[1];
    const float* bq = (const float*)d_in[2];
    const float* Wk = (const float*)d_in[3];
    const float* bk = (const float*)d_in[4];
    const float* Wv = (const float*)d_in[5];
    const float* bv = (const float*)d_in[6];
    const float* W1 = (const float*)d_in[7];
    const float* b1 = (const float*)d_in[8];
    const float* W2 = (const float*)d_in[9];
    const float* b2 = (const float*)d_in[10];
    float* y = (float*)d_out;

    float *q, *k, *v, *o, *hb;
    cudaGetSymbolAddress((void**)&q,  g_q);
    cudaGetSymbolAddress((void**)&k,  g_k);
    cudaGetSymbolAddress((void**)&v,  g_v);
    cudaGetSymbolAddress((void**)&o,  g_o);
    cudaGetSymbolAddress((void**)&hb, g_h);

    dim3 gblk(256);
    dim3 ggrid(DIM / BN, ROWS / BM);   // (8, 32)

    // QKV projections
    sgemm_nt<EPI_QSCALE><<<ggrid, gblk>>>(x, Wq, bq, q, ROWS, DIM, DIM, nullptr, nullptr);
    sgemm_nt<EPI_PLAIN ><<<ggrid, gblk>>>(x, Wk, bk, k, ROWS, DIM, DIM, nullptr, nullptr);
    sgemm_nt<EPI_PLAIN ><<<ggrid, gblk>>>(x, Wv, bv, v, ROWS, DIM, DIM, nullptr, nullptr);

    // KV = k^T v per (b,h)
    zero_kv_kernel<<<(BATCH * NH * HD * HD) / 256, 256>>>();
    kv_kernel<<<dim3(BATCH * NH, SEQ / 256), 256>>>();

    // out = q @ KV
    attn_out_kernel<<<dim3(ROWS / 64, NH), 256>>>();

    // MLP
    sgemm_nt<EPI_GELU ><<<ggrid, gblk>>>(o,  W1, b1, hb, ROWS, DIM, DIM, nullptr, nullptr);
    sgemm_nt<EPI_RESID><<<ggrid, gblk>>>(hb, W2, b2, y,  ROWS, DIM, DIM, x, o);
}

// round 9
// speedup vs baseline: 1.8958x; 1.8958x over previous
#include <cuda_runtime.h>
#include <cuda_bf16.h>
#include <math.h>
#include <stdint.h>

#define DIM   1024
#define NH    16
#define HD    64
#define SEQ   2048
#define BATCH 2
#define ROWS  (BATCH * SEQ)      // 4096
#define QSCALE 0.125f

// ---------------- scratch (static device globals; no allocation) -------------
__device__ float g_q[ROWS * DIM];
__device__ float g_k[ROWS * DIM];
__device__ float g_v[ROWS * DIM];
__device__ float g_o[ROWS * DIM];
__device__ float g_h[ROWS * DIM];
__device__ float g_kv[BATCH * NH * HD * HD];

__device__ unsigned short g_xh[ROWS * DIM], g_xl[ROWS * DIM];
__device__ unsigned short g_oh[ROWS * DIM], g_ol[ROWS * DIM];
__device__ unsigned short g_hh[ROWS * DIM], g_hl[ROWS * DIM];
__device__ unsigned short g_wh[5][DIM * DIM];
__device__ unsigned short g_wl[5][DIM * DIM];

// ============================ helpers ========================================
__device__ __forceinline__ uint32_t smem_u32(const void* p) {
    uint32_t a;
    asm("{ .reg .u64 t; cvta.to.shared.u64 t, %1; cvt.u32.u64 %0, t; }"
        : "=r"(a) : "l"(p));
    return a;
}
__device__ __forceinline__ void cp_async16(uint32_t dst, const void* src) {
    asm volatile("cp.async.cg.shared.global [%0], [%1], 16;"
                 :: "r"(dst), "l"(__cvta_generic_to_global(src)));
}
__device__ __forceinline__ void ldsm4(uint32_t* r, uint32_t addr) {
    asm volatile("ldmatrix.sync.aligned.m8n8.x4.shared.b16 {%0,%1,%2,%3}, [%4];"
                 : "=r"(r[0]), "=r"(r[1]), "=r"(r[2]), "=r"(r[3]) : "r"(addr));
}
__device__ __forceinline__ void mma16816(float* d, const uint32_t* a,
                                         uint32_t b0, uint32_t b1) {
    asm volatile(
        "mma.sync.aligned.m16n8k16.row.col.f32.bf16.bf16.f32 "
        "{%0,%1,%2,%3}, {%4,%5,%6,%7}, {%8,%9}, {%0,%1,%2,%3};"
        : "+f"(d[0]), "+f"(d[1]), "+f"(d[2]), "+f"(d[3])
        : "r"(a[0]), "r"(a[1]), "r"(a[2]), "r"(a[3]), "r"(b0), "r"(b1));
}

// ====================== bf16x3 HMMA GEMM =====================================
// C[4096,1024] = A[4096,1024] @ W[1024,1024]^T, A/W as bf16 (hi,lo) splits.
// CTA 128x128, 8 warps (4M x 2N), warp tile 32x64, BK=32, 3-stage cp.async.
#define GBM 128
#define GBN 128
#define GBK 32
#define KDIM 1024
#define NKS (KDIM / GBK)        // 32 k-stages
#define RSB 80                  // smem row stride bytes (32 bf16 + 8 pad)
#define TILE_B (128 * RSB)      // 10240 per operand tile
#define STAGE_B (4 * TILE_B)    // Ah, Al, Wh, Wl
#define NSTG 3
#define GSMEM_TOTAL (NSTG * STAGE_B)   // 122880

enum { EPI_PLAIN = 0, EPI_QSCALE = 1, EPI_GELU = 2, EPI_RESID = 3 };

template <int EPI>
__global__ __launch_bounds__(256, 1) void gemm_bf16x3(
    const unsigned short* __restrict__ Ah, const unsigned short* __restrict__ Al,
    const unsigned short* __restrict__ Wh, const unsigned short* __restrict__ Wl,
    const float* __restrict__ bias, float* __restrict__ C,
    const float* __restrict__ r1, const float* __restrict__ r2)
{
    extern __shared__ char smem[];
    const uint32_t sb = smem_u32(smem);
    const int tid  = threadIdx.x;
    const int lane = tid & 31;
    const int wid  = tid >> 5;
    const int wm   = wid & 3;          // 4 warps along M
    const int wn   = wid >> 2;         // 2 warps along N
    const int row0 = blockIdx.y * GBM;
    const int col0 = blockIdx.x * GBN;

    float acc[2][8][4];
    #pragma unroll
    for (int i = 0; i < 2; i++)
        #pragma unroll
        for (int j = 0; j < 8; j++)
            #pragma unroll
            for (int t = 0; t < 4; t++) acc[i][j][t] = 0.0f;

    // per-thread cp.async mapping: row = tid>>1, two 16B chunks
    const int cr  = tid >> 1;
    const int cc0 = (tid & 1) * 2;     // chunk index 0..3 (16B units)

    auto load_stage = [&](int s, int slot) {
        const uint32_t base = sb + slot * STAGE_B;
        const int k0 = s * GBK;
        const size_t ga = (size_t)(row0 + cr) * KDIM + k0 + cc0 * 8;
        const size_t gw = (size_t)(col0 + cr) * KDIM + k0 + cc0 * 8;
        const uint32_t ds = base + cr * RSB + cc0 * 16;
        cp_async16(ds + 0 * TILE_B,      Ah + ga);
        cp_async16(ds + 0 * TILE_B + 16, Ah + ga + 8);
        cp_async16(ds + 1 * TILE_B,      Al + ga);
        cp_async16(ds + 1 * TILE_B + 16, Al + ga + 8);
        cp_async16(ds + 2 * TILE_B,      Wh + gw);
        cp_async16(ds + 2 * TILE_B + 16, Wh + gw + 8);
        cp_async16(ds + 3 * TILE_B,      Wl + gw);
        cp_async16(ds + 3 * TILE_B + 16, Wl + gw + 8);
    };

    // prologue: stages 0 and 1
    load_stage(0, 0);
    asm volatile("cp.async.commit_group;" ::: "memory");
    load_stage(1, 1);
    asm volatile("cp.async.commit_group;" ::: "memory");

    // ldmatrix lane address components
    const int lrow   = lane & 15;
    const int lchunk = (lane >> 4) * 16;
    const uint32_t a_off = (uint32_t)((wm * 32 + lrow) * RSB + lchunk);
    const uint32_t b_off = (uint32_t)((wn * 64 + lrow) * RSB + lchunk);

    for (int s = 0; s < NKS; s++) {
        asm volatile("cp.async.wait_group 1;" ::: "memory");
        __syncthreads();
        if (s + 2 < NKS) load_stage(s + 2, (s + 2) % NSTG);
        asm volatile("cp.async.commit_group;" ::: "memory");

        const uint32_t base = sb + (s % NSTG) * STAGE_B;
        #pragma unroll
        for (int kk = 0; kk < 2; kk++) {
            const uint32_t ko = kk * 32;   // 16 bf16 = 32 bytes
            uint32_t ah[2][4], al[2][4], wh[4][4], wl[4][4];
            #pragma unroll
            for (int mt = 0; mt < 2; mt++) {
                ldsm4(ah[mt], base + 0 * TILE_B + a_off + mt * 16 * RSB + ko);
                ldsm4(al[mt], base + 1 * TILE_B + a_off + mt * 16 * RSB + ko);
            }
            #pragma unroll
            for (int nt2 = 0; nt2 < 4; nt2++) {
                ldsm4(wh[nt2], base + 2 * TILE_B + b_off + nt2 * 16 * RSB + ko);
                ldsm4(wl[nt2], base + 3 * TILE_B + b_off + nt2 * 16 * RSB + ko);
            }
            #pragma unroll
            for (int mt = 0; mt < 2; mt++) {
                #pragma unroll
                for (int nt2 = 0; nt2 < 4; nt2++) {
                    // n8 sub-frag 0: regs {0,2}; sub-frag 1: regs {1,3}
                    mma16816(acc[mt][nt2 * 2 + 0], ah[mt], wh[nt2][0], wh[nt2][2]);
                    mma16816(acc[mt][nt2 * 2 + 0], ah[mt], wl[nt2][0], wl[nt2][2]);
                    mma16816(acc[mt][nt2 * 2 + 0], al[mt], wh[nt2][0], wh[nt2][2]);
                    mma16816(acc[mt][nt2 * 2 + 1], ah[mt], wh[nt2][1], wh[nt2][3]);
                    mma16816(acc[mt][nt2 * 2 + 1], ah[mt], wl[nt2][1], wl[nt2][3]);
                    mma16816(acc[mt][nt2 * 2 + 1], al[mt], wh[nt2][1], wh[nt2][3]);
                }
            }
        }
    }

    // ---------------- epilogue (from accumulator regs) -----------------------
    const int rb = row0 + wm * 32 + (lane >> 2);
    const int cb = col0 + wn * 64 + (lane & 3) * 2;

    #pragma unroll
    for (int mt = 0; mt < 2; mt++) {
        #pragma unroll
        for (int nt = 0; nt < 8; nt++) {
            const int c = cb + nt * 8;
            const float2 bv = *reinterpret_cast<const float2*>(&bias[c]);
            #pragma unroll
            for (int rh = 0; rh < 2; rh++) {
                const int r = rb + mt * 16 + rh * 8;
                float e0 = acc[mt][nt][rh * 2 + 0] + bv.x;
                float e1 = acc[mt][nt][rh * 2 + 1] + bv.y;
                if (EPI == EPI_QSCALE) {
                    e0 *= QSCALE; e1 *= QSCALE;
                } else if (EPI == EPI_GELU) {
                    e0 = 0.5f * e0 * (1.0f + erff(e0 * 0.70710678118654752f));
                    e1 = 0.5f * e1 * (1.0f + erff(e1 * 0.70710678118654752f));
                } else if (EPI == EPI_RESID) {
                    const size_t idx = (size_t)r * DIM + c;
                    float2 a = *reinterpret_cast<const float2*>(&r1[idx]);
                    float2 b = *reinterpret_cast<const float2*>(&r2[idx]);
                    e0 += a.x + b.x; e1 += a.y + b.y;
                }
                *reinterpret_cast<float2*>(&C[(size_t)r * DIM + c]) =
                    make_float2(e0, e1);
            }
        }
    }
}

// ---------------- fp32 -> bf16 (hi, lo) split --------------------------------
__global__ __launch_bounds__(256) void split_bf16_kernel(
    const float* __restrict__ src,
    unsigned short* __restrict__ hi, unsigned short* __restrict__ lo, int n4)
{
    int i = blockIdx.x * blockDim.x + threadIdx.x;
    if (i >= n4) return;
    float4 v = reinterpret_cast<const float4*>(src)[i];
    float f[4] = {v.x, v.y, v.z, v.w};
    unsigned short hs[4], ls[4];
    #pragma unroll
    for (int j = 0; j < 4; j++) {
        __nv_bfloat16 hb = __float2bfloat16(f[j]);
        float rr = f[j] - __bfloat162float(hb);
        __nv_bfloat16 lb = __float2bfloat16(rr);
        hs[j] = __bfloat16_as_ushort(hb);
        ls[j] = __bfloat16_as_ushort(lb);
    }
    reinterpret_cast<ushort4*>(hi)[i] = make_ushort4(hs[0], hs[1], hs[2], hs[3]);
    reinterpret_cast<ushort4*>(lo)[i] = make_ushort4(ls[0], ls[1], ls[2], ls[3]);
}

// ---------------- zero KV ----------------------------------------------------
__global__ void zero_kv_kernel()
{
    int i = blockIdx.x * blockDim.x + threadIdx.x;
    g_kv[i] = 0.0f;
}

// ---------------- KV[b,h] = sum_s k[b,s,h,:]^T v[b,s,h,:] --------------------
__global__ __launch_bounds__(256) void kv_kernel()
{
    const int bh = blockIdx.x;
    const int b  = bh / NH;
    const int h  = bh % NH;
    const int s0 = blockIdx.y * 256;
    const int tid = threadIdx.x;

    __shared__ float ks[8][64];
    __shared__ float vs[8][64];

    const int d1 = (tid >> 4) * 4;
    const int d2 = (tid & 15) * 4;

    float acc[4][4] = {};

    const size_t base = (size_t)b * SEQ * DIM + h * HD;
    const int lrow = tid >> 5;
    const int lcol = (tid & 31) * 2;

    for (int s = s0; s < s0 + 256; s += 8) {
        const float* kr = g_k + base + (size_t)(s + lrow) * DIM;
        const float* vr = g_v + base + (size_t)(s + lrow) * DIM;
        *reinterpret_cast<float2*>(&ks[lrow][lcol]) =
            *reinterpret_cast<const float2*>(&kr[lcol]);
        *reinterpret_cast<float2*>(&vs[lrow][lcol]) =
            *reinterpret_cast<const float2*>(&vr[lcol]);
        __syncthreads();
        #pragma unroll
        for (int ss = 0; ss < 8; ss++) {
            float4 k4 = *reinterpret_cast<const float4*>(&ks[ss][d1]);
            float4 v4 = *reinterpret_cast<const float4*>(&vs[ss][d2]);
            float ka[4] = {k4.x, k4.y, k4.z, k4.w};
            float va[4] = {v4.x, v4.y, v4.z, v4.w};
            #pragma unroll
            for (int i = 0; i < 4; i++)
                #pragma unroll
                for (int j = 0; j < 4; j++)
                    acc[i][j] += ka[i] * va[j];
        }
        __syncthreads();
    }

    float* dst = g_kv + (size_t)bh * (HD * HD);
    #pragma unroll
    for (int i = 0; i < 4; i++)
        #pragma unroll
        for (int j = 0; j < 4; j++)
            atomicAdd(&dst[(d1 + i) * HD + d2 + j], acc[i][j]);
}

// ---------------- out[b,s,h,:] = q[b,s,h,:] @ KV[b,h] ------------------------
__global__ __launch_bounds__(256) void attn_out_kernel()
{
    const int h  = blockIdx.y;
    const int r0 = blockIdx.x * 64;
    const int b  = r0 >> 11;
    const int tid = threadIdx.x;

    __shared__ float kvs[64][64];
    __shared__ float qs[64][65];

    {
        const float4* src = reinterpret_cast<const float4*>(
            g_kv + (size_t)(b * NH + h) * (HD * HD));
        float4* dst = reinterpret_cast<float4*>(&kvs[0][0]);
        for (int i = tid; i < 1024; i += 256) dst[i] = src[i];
    }
    for (int i = tid; i < 1024; i += 256) {
        int r  = i >> 4;
        int c4 = (i & 15) * 4;
        float4 t = *reinterpret_cast<const float4*>(
            &g_q[(size_t)(r0 + r) * DIM + h * HD + c4]);
        qs[c4 + 0][r] = t.x; qs[c4 + 1][r] = t.y;
        qs[c4 + 2][r] = t.z; qs[c4 + 3][r] = t.w;
    }
    __syncthreads();

    const int r4 = (tid >> 4) * 4;
    const int c4 = (tid & 15) * 4;

    float acc[4][4] = {};
    #pragma unroll 4
    for (int d = 0; d < 64; d++) {
        float qv[4];
        #pragma unroll
        for (int i = 0; i < 4; i++) qv[i] = qs[d][r4 + i];
        float4 kv4 = *reinterpret_cast<const float4*>(&kvs[d][c4]);
        float kvv[4] = {kv4.x, kv4.y, kv4.z, kv4.w};
        #pragma unroll
        for (int i = 0; i < 4; i++)
            #pragma unroll
            for (int j = 0; j < 4; j++)
                acc[i][j] += qv[i] * kvv[j];
    }

    #pragma unroll
    for (int i = 0; i < 4; i++) {
        float4 o = make_float4(acc[i][0], acc[i][1], acc[i][2], acc[i][3]);
        *reinterpret_cast<float4*>(
            &g_o[(size_t)(r0 + r4 + i) * DIM + h * HD + c4]) = o;
    }
}

// ---------------- launch -----------------------------------------------------
extern "C" void kernel_launch(void* const* d_in, const int* in_sizes, int n_in,
                              void* d_out, int out_size)
{
    const float* x  = (const float*)d_in[0];
    const float* Wq = (const float*)d_in[1];
    const float* bq = (const float*)d_in[2];
    const float* Wk = (const float*)d_in[3];
    const float* bk = (const float*)d_in[4];
    const float* Wv = (const float*)d_in[5];
    const float* bv = (const float*)d_in[6];
    const float* W1 = (const float*)d_in[7];
    const float* b1 = (const float*)d_in[8];
    const float* W2 = (const float*)d_in[9];
    const float* b2 = (const float*)d_in[10];
    float* y = (float*)d_out;

    float *q, *k, *v, *o, *hb;
    cudaGetSymbolAddress((void**)&q,  g_q);
    cudaGetSymbolAddress((void**)&k,  g_k);
    cudaGetSymbolAddress((void**)&v,  g_v);
    cudaGetSymbolAddress((void**)&o,  g_o);
    cudaGetSymbolAddress((void**)&hb, g_h);
    unsigned short *xh, *xl, *oh, *ol, *hh, *hl, *wh, *wl;
    cudaGetSymbolAddress((void**)&xh, g_xh);
    cudaGetSymbolAddress((void**)&xl, g_xl);
    cudaGetSymbolAddress((void**)&oh, g_oh);
    cudaGetSymbolAddress((void**)&ol, g_ol);
    cudaGetSymbolAddress((void**)&hh, g_hh);
    cudaGetSymbolAddress((void**)&hl, g_hl);
    cudaGetSymbolAddress((void**)&wh, g_wh);
    cudaGetSymbolAddress((void**)&wl, g_wl);

    cudaFuncSetAttribute(gemm_bf16x3<EPI_PLAIN>,  cudaFuncAttributeMaxDynamicSharedMemorySize, GSMEM_TOTAL);
    cudaFuncSetAttribute(gemm_bf16x3<EPI_QSCALE>, cudaFuncAttributeMaxDynamicSharedMemorySize, GSMEM_TOTAL);
    cudaFuncSetAttribute(gemm_bf16x3<EPI_GELU>,   cudaFuncAttributeMaxDynamicSharedMemorySize, GSMEM_TOTAL);
    cudaFuncSetAttribute(gemm_bf16x3<EPI_RESID>,  cudaFuncAttributeMaxDynamicSharedMemorySize, GSMEM_TOTAL);

    const int NW  = DIM * DIM;
    const int n4a = ROWS * DIM / 4;
    const int n4w = NW / 4;

    split_bf16_kernel<<<n4a / 256, 256>>>(x,  xh, xl, n4a);
    split_bf16_kernel<<<n4w / 256, 256>>>(Wq, wh + 0 * NW, wl + 0 * NW, n4w);
    split_bf16_kernel<<<n4w / 256, 256>>>(Wk, wh + 1 * NW, wl + 1 * NW, n4w);
    split_bf16_kernel<<<n4w / 256, 256>>>(Wv, wh + 2 * NW, wl + 2 * NW, n4w);
    split_bf16_kernel<<<n4w / 256, 256>>>(W1, wh + 3 * NW, wl + 3 * NW, n4w);
    split_bf16_kernel<<<n4w / 256, 256>>>(W2, wh + 4 * NW, wl + 4 * NW, n4w);

    dim3 ggrid(DIM / GBN, ROWS / GBM);   // (8, 32) = 256 CTAs

    gemm_bf16x3<EPI_QSCALE><<<ggrid, 256, GSMEM_TOTAL>>>(xh, xl, wh + 0 * NW, wl + 0 * NW, bq, q, nullptr, nullptr);
    gemm_bf16x3<EPI_PLAIN ><<<ggrid, 256, GSMEM_TOTAL>>>(xh, xl, wh + 1 * NW, wl + 1 * NW, bk, k, nullptr, nullptr);
    gemm_bf16x3<EPI_PLAIN ><<<ggrid, 256, GSMEM_TOTAL>>>(xh, xl, wh + 2 * NW, wl + 2 * NW, bv, v, nullptr, nullptr);

    zero_kv_kernel<<<(BATCH * NH * HD * HD) / 256, 256>>>();
    kv_kernel<<<dim3(BATCH * NH, SEQ / 256), 256>>>();
    attn_out_kernel<<<dim3(ROWS / 64, NH), 256>>>();

    split_bf16_kernel<<<n4a / 256, 256>>>(o, oh, ol, n4a);
    gemm_bf16x3<EPI_GELU ><<<ggrid, 256, GSMEM_TOTAL>>>(oh, ol, wh + 3 * NW, wl + 3 * NW, b1, hb, nullptr, nullptr);
    split_bf16_kernel<<<n4a / 256, 256>>>(hb, hh, hl, n4a);
    gemm_bf16x3<EPI_RESID><<<ggrid, 256, GSMEM_TOTAL>>>(hh, hl, wh + 4 * NW, wl + 4 * NW, b2, y, x, o);
}

// round 13
// speedup vs baseline: 1.9176x; 1.0115x over previous
#include <cuda_runtime.h>
#include <cuda_bf16.h>
#include <math.h>
#include <stdint.h>

#define DIM   1024
#define NH    16
#define HD    64
#define SEQ   2048
#define BATCH 2
#define ROWS  (BATCH * SEQ)      // 4096
#define QSCALE 0.125f

// ---------------- scratch (static device globals; no allocation) -------------
__device__ float g_q[ROWS * DIM];
__device__ float g_k[ROWS * DIM];
__device__ float g_v[ROWS * DIM];
__device__ float g_o[ROWS * DIM];
__device__ float g_kv[BATCH * NH * HD * HD];

__device__ unsigned short g_xh[ROWS * DIM], g_xl[ROWS * DIM];
__device__ unsigned short g_oh[ROWS * DIM], g_ol[ROWS * DIM];
__device__ unsigned short g_hh[ROWS * DIM], g_hl[ROWS * DIM];
__device__ unsigned short g_wh[5][DIM * DIM];
__device__ unsigned short g_wl[5][DIM * DIM];

// ============================ helpers ========================================
__device__ __forceinline__ uint32_t smem_u32(const void* p) {
    uint32_t a;
    asm("{ .reg .u64 t; cvta.to.shared.u64 t, %1; cvt.u32.u64 %0, t; }"
        : "=r"(a) : "l"(p));
    return a;
}
__device__ __forceinline__ void cp_async16(uint32_t dst, const void* src) {
    asm volatile("cp.async.cg.shared.global [%0], [%1], 16;"
                 :: "r"(dst), "l"(__cvta_generic_to_global(src)));
}
__device__ __forceinline__ void ldsm4(uint32_t* r, uint32_t addr) {
    asm volatile("ldmatrix.sync.aligned.m8n8.x4.shared.b16 {%0,%1,%2,%3}, [%4];"
                 : "=r"(r[0]), "=r"(r[1]), "=r"(r[2]), "=r"(r[3]) : "r"(addr));
}
__device__ __forceinline__ void mma16816(float* d, const uint32_t* a,
                                         uint32_t b0, uint32_t b1) {
    asm volatile(
        "mma.sync.aligned.m16n8k16.row.col.f32.bf16.bf16.f32 "
        "{%0,%1,%2,%3}, {%4,%5,%6,%7}, {%8,%9}, {%0,%1,%2,%3};"
        : "+f"(d[0]), "+f"(d[1]), "+f"(d[2]), "+f"(d[3])
        : "r"(a[0]), "r"(a[1]), "r"(a[2]), "r"(a[3]), "r"(b0), "r"(b1));
}
__device__ __forceinline__ void split1(float f, unsigned short& h, unsigned short& l) {
    __nv_bfloat16 hb = __float2bfloat16(f);
    float rr = f - __bfloat162float(hb);
    h = __bfloat16_as_ushort(hb);
    l = __bfloat16_as_ushort(__float2bfloat16(rr));
}

// ====================== bf16x3 HMMA GEMM =====================================
// CTA tile 128x256, 8 warps (2M x 4N), warp tile 64x64, BK=32, 3-stage cp.async.
#define GBM 128
#define GBN 256
#define GBK 32
#define KDIM 1024
#define NKS (KDIM / GBK)          // 32
#define RSB 80                    // smem row stride (64B data + 16B pad)
#define A_TILE_B (128 * RSB)      // 10240
#define W_TILE_B (256 * RSB)      // 20480
#define ST_AH 0
#define ST_AL A_TILE_B
#define ST_WH (2 * A_TILE_B)
#define ST_WL (2 * A_TILE_B + W_TILE_B)
#define STAGE_B (2 * A_TILE_B + 2 * W_TILE_B)   // 61440
#define NSTG 3
#define GSMEM_TOTAL (NSTG * STAGE_B)            // 184320

// mainloop: fills acc[4][8][4] for warp tile 64x64
__device__ __forceinline__ void gemm_mainloop(
    const unsigned short* __restrict__ Ah, const unsigned short* __restrict__ Al,
    const unsigned short* __restrict__ Wh, const unsigned short* __restrict__ Wl,
    uint32_t sb, int row0, int col0, int tid, float acc[4][8][4])
{
    const int lane = tid & 31;
    const int wid  = tid >> 5;
    const int wm   = wid & 1;
    const int wn   = wid >> 1;

    // cp.async mappings
    const int acr = tid >> 1;            // A row 0..127
    const int acc0 = (tid & 1) * 2;      // A chunk 0 or 2

    auto load_stage = [&](int s, int slot) {
        const uint32_t base = sb + slot * STAGE_B;
        const int k0 = s * GBK;
        {   // A hi/lo: 2 chunks per thread
            const size_t ga = (size_t)(row0 + acr) * KDIM + k0 + acc0 * 8;
            const uint32_t ds = base + acr * RSB + acc0 * 16;
            cp_async16(ds + ST_AH,      Ah + ga);
            cp_async16(ds + ST_AH + 16, Ah + ga + 8);
            cp_async16(ds + ST_AL,      Al + ga);
            cp_async16(ds + ST_AL + 16, Al + ga + 8);
        }
        {   // W hi/lo: full 64B row per thread
            const size_t gw = (size_t)(col0 + tid) * KDIM + k0;
            const uint32_t ds = base + tid * RSB;
            #pragma unroll
            for (int c = 0; c < 4; c++) {
                cp_async16(ds + ST_WH + c * 16, Wh + gw + c * 8);
                cp_async16(ds + ST_WL + c * 16, Wl + gw + c * 8);
            }
        }
        asm volatile("cp.async.commit_group;" ::: "memory");
    };

    load_stage(0, 0);
    load_stage(1, 1);

    const int lrow   = lane & 15;
    const int lchunk = (lane >> 4) * 16;
    const uint32_t a_off = (uint32_t)((wm * 64 + lrow) * RSB + lchunk);
    const uint32_t b_off = (uint32_t)((wn * 64 + lrow) * RSB + lchunk);

    for (int s = 0; s < NKS; s++) {
        asm volatile("cp.async.wait_group 1;" ::: "memory");
        __syncthreads();
        if (s + 2 < NKS) load_stage(s + 2, (s + 2) % NSTG);
        else asm volatile("cp.async.commit_group;" ::: "memory");

        const uint32_t base = sb + (s % NSTG) * STAGE_B;
        #pragma unroll
        for (int kk = 0; kk < 2; kk++) {
            const uint32_t ko = kk * 32;
            uint32_t ah[4][4], al[4][4], wh[4][4], wl[4][4];
            #pragma unroll
            for (int mt = 0; mt < 4; mt++) {
                ldsm4(ah[mt], base + ST_AH + a_off + mt * 16 * RSB + ko);
                ldsm4(al[mt], base + ST_AL + a_off + mt * 16 * RSB + ko);
            }
            #pragma unroll
            for (int nt = 0; nt < 4; nt++) {
                ldsm4(wh[nt], base + ST_WH + b_off + nt * 16 * RSB + ko);
                ldsm4(wl[nt], base + ST_WL + b_off + nt * 16 * RSB + ko);
            }
            #pragma unroll
            for (int mt = 0; mt < 4; mt++) {
                #pragma unroll
                for (int nt = 0; nt < 4; nt++) {
                    mma16816(acc[mt][nt * 2 + 0], ah[mt], wh[nt][0], wh[nt][2]);
                    mma16816(acc[mt][nt * 2 + 0], ah[mt], wl[nt][0], wl[nt][2]);
                    mma16816(acc[mt][nt * 2 + 0], al[mt], wh[nt][0], wh[nt][2]);
                    mma16816(acc[mt][nt * 2 + 1], ah[mt], wh[nt][1], wh[nt][3]);
                    mma16816(acc[mt][nt * 2 + 1], ah[mt], wl[nt][1], wl[nt][3]);
                    mma16816(acc[mt][nt * 2 + 1], al[mt], wh[nt][1], wh[nt][3]);
                }
            }
        }
    }
}

// ---------------- combined QKV GEMM (grid.z = 0:q 1:k 2:v) -------------------
__global__ __launch_bounds__(256, 1) void gemm_qkv(
    const unsigned short* __restrict__ Ah, const unsigned short* __restrict__ Al,
    const unsigned short* __restrict__ WhB, const unsigned short* __restrict__ WlB,
    const float* __restrict__ b0, const float* __restrict__ b1,
    const float* __restrict__ b2,
    float* __restrict__ c0, float* __restrict__ c1, float* __restrict__ c2)
{
    extern __shared__ char smem[];
    const uint32_t sb = smem_u32(smem);
    const int tid  = threadIdx.x;
    const int lane = tid & 31;
    const int wid  = tid >> 5;
    const int z    = blockIdx.z;
    const int row0 = blockIdx.y * GBM;
    const int col0 = blockIdx.x * GBN;
    const int NW   = DIM * DIM;

    const unsigned short* Wh = WhB + (size_t)z * NW;
    const unsigned short* Wl = WlB + (size_t)z * NW;
    const float* bias = (z == 0) ? b0 : (z == 1) ? b1 : b2;
    float* C = (z == 0) ? c0 : (z == 1) ? c1 : c2;
    const float scale = (z == 0) ? QSCALE : 1.0f;

    float acc[4][8][4];
    #pragma unroll
    for (int i = 0; i < 4; i++)
        #pragma unroll
        for (int j = 0; j < 8; j++)
            #pragma unroll
            for (int t = 0; t < 4; t++) acc[i][j][t] = 0.0f;

    gemm_mainloop(Ah, Al, Wh, Wl, sb, row0, col0, tid, acc);

    const int rb = row0 + (wid & 1) * 64 + (lane >> 2);
    const int cb = col0 + (wid >> 1) * 64 + (lane & 3) * 2;
    #pragma unroll
    for (int mt = 0; mt < 4; mt++) {
        #pragma unroll
        for (int nt = 0; nt < 8; nt++) {
            const int c = cb + nt * 8;
            const float2 bv = *reinterpret_cast<const float2*>(&bias[c]);
            #pragma unroll
            for (int rh = 0; rh < 2; rh++) {
                const int r = rb + mt * 16 + rh * 8;
                float e0 = (acc[mt][nt][rh * 2 + 0] + bv.x) * scale;
                float e1 = (acc[mt][nt][rh * 2 + 1] + bv.y) * scale;
                *reinterpret_cast<float2*>(&C[(size_t)r * DIM + c]) =
                    make_float2(e0, e1);
            }
        }
    }
}

// ---------------- GELU GEMM: writes bf16 (hi,lo) split only ------------------
__global__ __launch_bounds__(256, 1) void gemm_gelu(
    const unsigned short* __restrict__ Ah, const unsigned short* __restrict__ Al,
    const unsigned short* __restrict__ Wh, const unsigned short* __restrict__ Wl,
    const float* __restrict__ bias,
    unsigned short* __restrict__ Oh, unsigned short* __restrict__ Ol)
{
    extern __shared__ char smem[];
    const uint32_t sb = smem_u32(smem);
    const int tid  = threadIdx.x;
    const int lane = tid & 31;
    const int wid  = tid >> 5;
    const int row0 = blockIdx.y * GBM;
    const int col0 = blockIdx.x * GBN;

    float acc[4][8][4];
    #pragma unroll
    for (int i = 0; i < 4; i++)
        #pragma unroll
        for (int j = 0; j < 8; j++)
            #pragma unroll
            for (int t = 0; t < 4; t++) acc[i][j][t] = 0.0f;

    gemm_mainloop(Ah, Al, Wh, Wl, sb, row0, col0, tid, acc);

    const int rb = row0 + (wid & 1) * 64 + (lane >> 2);
    const int cb = col0 + (wid >> 1) * 64 + (lane & 3) * 2;
    #pragma unroll
    for (int mt = 0; mt < 4; mt++) {
        #pragma unroll
        for (int nt = 0; nt < 8; nt++) {
            const int c = cb + nt * 8;
            const float2 bv = *reinterpret_cast<const float2*>(&bias[c]);
            #pragma unroll
            for (int rh = 0; rh < 2; rh++) {
                const int r = rb + mt * 16 + rh * 8;
                float e0 = acc[mt][nt][rh * 2 + 0] + bv.x;
                float e1 = acc[mt][nt][rh * 2 + 1] + bv.y;
                e0 = 0.5f * e0 * (1.0f + erff(e0 * 0.70710678118654752f));
                e1 = 0.5f * e1 * (1.0f + erff(e1 * 0.70710678118654752f));
                unsigned short h0, l0, h1, l1;
                split1(e0, h0, l0);
                split1(e1, h1, l1);
                const size_t idx = (size_t)r * DIM + c;
                *reinterpret_cast<ushort2*>(&Oh[idx]) = make_ushort2(h0, h1);
                *reinterpret_cast<ushort2*>(&Ol[idx]) = make_ushort2(l0, l1);
            }
        }
    }
}

// ---------------- final GEMM: y = x + o + (h @ W2^T + b2) --------------------
__global__ __launch_bounds__(256, 1) void gemm_resid(
    const unsigned short* __restrict__ Ah, const unsigned short* __restrict__ Al,
    const unsigned short* __restrict__ Wh, const unsigned short* __restrict__ Wl,
    const float* __restrict__ bias, float* __restrict__ C,
    const float* __restrict__ r1, const float* __restrict__ r2)
{
    extern __shared__ char smem[];
    const uint32_t sb = smem_u32(smem);
    const int tid  = threadIdx.x;
    const int lane = tid & 31;
    const int wid  = tid >> 5;
    const int row0 = blockIdx.y * GBM;
    const int col0 = blockIdx.x * GBN;

    float acc[4][8][4];
    #pragma unroll
    for (int i = 0; i < 4; i++)
        #pragma unroll
        for (int j = 0; j < 8; j++)
            #pragma unroll
            for (int t = 0; t < 4; t++) acc[i][j][t] = 0.0f;

    gemm_mainloop(Ah, Al, Wh, Wl, sb, row0, col0, tid, acc);

    const int rb = row0 + (wid & 1) * 64 + (lane >> 2);
    const int cb = col0 + (wid >> 1) * 64 + (lane & 3) * 2;
    #pragma unroll
    for (int mt = 0; mt < 4; mt++) {
        #pragma unroll
        for (int nt = 0; nt < 8; nt++) {
            const int c = cb + nt * 8;
            const float2 bv = *reinterpret_cast<const float2*>(&bias[c]);
            #pragma unroll
            for (int rh = 0; rh < 2; rh++) {
                const int r = rb + mt * 16 + rh * 8;
                const size_t idx = (size_t)r * DIM + c;
                float2 a = *reinterpret_cast<const float2*>(&r1[idx]);
                float2 b = *reinterpret_cast<const float2*>(&r2[idx]);
                float e0 = acc[mt][nt][rh * 2 + 0] + bv.x + a.x + b.x;
                float e1 = acc[mt][nt][rh * 2 + 1] + bv.y + a.y + b.y;
                *reinterpret_cast<float2*>(&C[idx]) = make_float2(e0, e1);
            }
        }
    }
}

// ---------------- fp32 -> bf16 (hi, lo) split: x -----------------------------
__global__ __launch_bounds__(256) void split_bf16_kernel(
    const float* __restrict__ src,
    unsigned short* __restrict__ hi, unsigned short* __restrict__ lo)
{
    int i = blockIdx.x * blockDim.x + threadIdx.x;
    float4 v = reinterpret_cast<const float4*>(src)[i];
    float f[4] = {v.x, v.y, v.z, v.w};
    unsigned short hs[4], ls[4];
    #pragma unroll
    for (int j = 0; j < 4; j++) split1(f[j], hs[j], ls[j]);
    reinterpret_cast<ushort4*>(hi)[i] = make_ushort4(hs[0], hs[1], hs[2], hs[3]);
    reinterpret_cast<ushort4*>(lo)[i] = make_ushort4(ls[0], ls[1], ls[2], ls[3]);
}

// ---------------- split all 5 weights in one launch (grid.y selects) ---------
__global__ __launch_bounds__(256) void split_w_kernel(
    const float* __restrict__ w0, const float* __restrict__ w1,
    const float* __restrict__ w2, const float* __restrict__ w3,
    const float* __restrict__ w4,
    unsigned short* __restrict__ hiB, unsigned short* __restrict__ loB)
{
    const int z = blockIdx.y;
    const float* src = (z == 0) ? w0 : (z == 1) ? w1 : (z == 2) ? w2
                     : (z == 3) ? w3 : w4;
    const size_t NW = (size_t)DIM * DIM;
    unsigned short* hi = hiB + z * NW;
    unsigned short* lo = loB + z * NW;
    int i = blockIdx.x * blockDim.x + threadIdx.x;
    float4 v = reinterpret_cast<const float4*>(src)[i];
    float f[4] = {v.x, v.y, v.z, v.w};
    unsigned short hs[4], ls[4];
    #pragma unroll
    for (int j = 0; j < 4; j++) split1(f[j], hs[j], ls[j]);
    reinterpret_cast<ushort4*>(hi)[i] = make_ushort4(hs[0], hs[1], hs[2], hs[3]);
    reinterpret_cast<ushort4*>(lo)[i] = make_ushort4(ls[0], ls[1], ls[2], ls[3]);
}

// ---------------- zero KV ----------------------------------------------------
__global__ void zero_kv_kernel()
{
    int i = blockIdx.x * blockDim.x + threadIdx.x;
    g_kv[i] = 0.0f;
}

// ---------------- KV[b,h] = sum_s k[b,s,h,:]^T v[b,s,h,:] --------------------
__global__ __launch_bounds__(256) void kv_kernel()
{
    const int bh = blockIdx.x;
    const int b  = bh / NH;
    const int h  = bh % NH;
    const int s0 = blockIdx.y * 256;
    const int tid = threadIdx.x;

    __shared__ float ks[8][64];
    __shared__ float vs[8][64];

    const int d1 = (tid >> 4) * 4;
    const int d2 = (tid & 15) * 4;

    float acc[4][4] = {};

    const size_t base = (size_t)b * SEQ * DIM + h * HD;
    const int lrow = tid >> 5;
    const int lcol = (tid & 31) * 2;

    for (int s = s0; s < s0 + 256; s += 8) {
        const float* kr = g_k + base + (size_t)(s + lrow) * DIM;
        const float* vr = g_v + base + (size_t)(s + lrow) * DIM;
        *reinterpret_cast<float2*>(&ks[lrow][lcol]) =
            *reinterpret_cast<const float2*>(&kr[lcol]);
        *reinterpret_cast<float2*>(&vs[lrow][lcol]) =
            *reinterpret_cast<const float2*>(&vr[lcol]);
        __syncthreads();
        #pragma unroll
        for (int ss = 0; ss < 8; ss++) {
            float4 k4 = *reinterpret_cast<const float4*>(&ks[ss][d1]);
            float4 v4 = *reinterpret_cast<const float4*>(&vs[ss][d2]);
            float ka[4] = {k4.x, k4.y, k4.z, k4.w};
            float va[4] = {v4.x, v4.y, v4.z, v4.w};
            #pragma unroll
            for (int i = 0; i < 4; i++)
                #pragma unroll
                for (int j = 0; j < 4; j++)
                    acc[i][j] += ka[i] * va[j];
        }
        __syncthreads();
    }

    float* dst = g_kv + (size_t)bh * (HD * HD);
    #pragma unroll
    for (int i = 0; i < 4; i++)
        #pragma unroll
        for (int j = 0; j < 4; j++)
            atomicAdd(&dst[(d1 + i) * HD + d2 + j], acc[i][j]);
}

// ------- out = q @ KV; also writes bf16 split of out (fused) -----------------
__global__ __launch_bounds__(256) void attn_out_kernel()
{
    const int h  = blockIdx.y;
    const int r0 = blockIdx.x * 64;
    const int b  = r0 >> 11;
    const int tid = threadIdx.x;

    __shared__ float kvs[64][64];
    __shared__ float qs[64][65];

    {
        const float4* src = reinterpret_cast<const float4*>(
            g_kv + (size_t)(b * NH + h) * (HD * HD));
        float4* dst = reinterpret_cast<float4*>(&kvs[0][0]);
        for (int i = tid; i < 1024; i += 256) dst[i] = src[i];
    }
    for (int i = tid; i < 1024; i += 256) {
        int r  = i >> 4;
        int c4 = (i & 15) * 4;
        float4 t = *reinterpret_cast<const float4*>(
            &g_q[(size_t)(r0 + r) * DIM + h * HD + c4]);
        qs[c4 + 0][r] = t.x; qs[c4 + 1][r] = t.y;
        qs[c4 + 2][r] = t.z; qs[c4 + 3][r] = t.w;
    }
    __syncthreads();

    const int r4 = (tid >> 4) * 4;
    const int c4 = (tid & 15) * 4;

    float acc[4][4] = {};
    #pragma unroll 4
    for (int d = 0; d < 64; d++) {
        float qv[4];
        #pragma unroll
        for (int i = 0; i < 4; i++) qv[i] = qs[d][r4 + i];
        float4 kv4 = *reinterpret_cast<const float4*>(&kvs[d][c4]);
        float kvv[4] = {kv4.x, kv4.y, kv4.z, kv4.w};
        #pragma unroll
        for (int i = 0; i < 4; i++)
            #pragma unroll
            for (int j = 0; j < 4; j++)
                acc[i][j] += qv[i] * kvv[j];
    }

    #pragma unroll
    for (int i = 0; i < 4; i++) {
        const size_t idx = (size_t)(r0 + r4 + i) * DIM + h * HD + c4;
        float4 o = make_float4(acc[i][0], acc[i][1], acc[i][2], acc[i][3]);
        *reinterpret_cast<float4*>(&g_o[idx]) = o;
        unsigned short hs[4], ls[4];
        split1(o.x, hs[0], ls[0]); split1(o.y, hs[1], ls[1]);
        split1(o.z, hs[2], ls[2]); split1(o.w, hs[3], ls[3]);
        *reinterpret_cast<ushort4*>(&g_oh[idx]) = make_ushort4(hs[0], hs[1], hs[2], hs[3]);
        *reinterpret_cast<ushort4*>(&g_ol[idx]) = make_ushort4(ls[0], ls[1], ls[2], ls[3]);
    }
}

// ---------------- launch -----------------------------------------------------
extern "C" void kernel_launch(void* const* d_in, const int* in_sizes, int n_in,
                              void* d_out, int out_size)
{
    const float* x  = (const float*)d_in[0];
    const float* Wq = (const float*)d_in[1];
    const float* bq = (const float*)d_in[2];
    const float* Wk = (const float*)d_in[3];
    const float* bk = (const float*)d_in[4];
    const float* Wv = (const float*)d_in[5];
    const float* bv = (const float*)d_in[6];
    const float* W1 = (const float*)d_in[7];
    const float* b1 = (const float*)d_in[8];
    const float* W2 = (const float*)d_in[9];
    const float* b2 = (const float*)d_in[10];
    float* y = (float*)d_out;

    float *q, *k, *v, *o;
    cudaGetSymbolAddress((void**)&q, g_q);
    cudaGetSymbolAddress((void**)&k, g_k);
    cudaGetSymbolAddress((void**)&v, g_v);
    cudaGetSymbolAddress((void**)&o, g_o);
    unsigned short *xh, *xl, *oh, *ol, *hh, *hl, *wh, *wl;
    cudaGetSymbolAddress((void**)&xh, g_xh);
    cudaGetSymbolAddress((void**)&xl, g_xl);
    cudaGetSymbolAddress((void**)&oh, g_oh);
    cudaGetSymbolAddress((void**)&ol, g_ol);
    cudaGetSymbolAddress((void**)&hh, g_hh);
    cudaGetSymbolAddress((void**)&hl, g_hl);
    cudaGetSymbolAddress((void**)&wh, g_wh);
    cudaGetSymbolAddress((void**)&wl, g_wl);

    cudaFuncSetAttribute(gemm_qkv,   cudaFuncAttributeMaxDynamicSharedMemorySize, GSMEM_TOTAL);
    cudaFuncSetAttribute(gemm_gelu,  cudaFuncAttributeMaxDynamicSharedMemorySize, GSMEM_TOTAL);
    cudaFuncSetAttribute(gemm_resid, cudaFuncAttributeMaxDynamicSharedMemorySize, GSMEM_TOTAL);

    const int NW  = DIM * DIM;
    const int n4a = ROWS * DIM / 4;
    const int n4w = NW / 4;

    // splits: x + all 5 weights
    split_bf16_kernel<<<n4a / 256, 256>>>(x, xh, xl);
    split_w_kernel<<<dim3(n4w / 256, 5), 256>>>(Wq, Wk, Wv, W1, W2, wh, wl);

    // fused QKV projections (one launch, grid.z = 3)
    dim3 ggrid(DIM / GBN, ROWS / GBM);        // (4, 32) = 128 CTAs
    dim3 gqkv(DIM / GBN, ROWS / GBM, 3);      // 384 CTAs
    gemm_qkv<<<gqkv, 256, GSMEM_TOTAL>>>(xh, xl, wh, wl, bq, bk, bv, q, k, v);

    // attention via KV association (fp32)
    zero_kv_kernel<<<(BATCH * NH * HD * HD) / 256, 256>>>();
    kv_kernel<<<dim3(BATCH * NH, SEQ / 256), 256>>>();
    attn_out_kernel<<<dim3(ROWS / 64, NH), 256>>>();

    // MLP
    gemm_gelu<<<ggrid, 256, GSMEM_TOTAL>>>(oh, ol, wh + (size_t)3 * NW, wl + (size_t)3 * NW, b1, hh, hl);
    gemm_resid<<<ggrid, 256, GSMEM_TOTAL>>>(hh, hl, wh + (size_t)4 * NW, wl + (size_t)4 * NW, b2, y, x, o);
}